// round 3
// baseline (speedup 1.0000x reference)
#include <cuda_runtime.h>

#define N_CLASS  100
#define N_CENTER 4
#define HIDDEN   128
#define BATCH    2048
#define CHUNK    16

// Scratch (no device allocation allowed): per-class sample counts + index lists.
__device__ int g_count[N_CLASS];
__device__ int g_list[N_CLASS * BATCH];

__global__ void zero_counts_kernel() {
    int i = blockIdx.x * blockDim.x + threadIdx.x;
    if (i < N_CLASS) g_count[i] = 0;
}

__global__ void build_lists_kernel(const int* __restrict__ y) {
    int b = blockIdx.x * blockDim.x + threadIdx.x;
    if (b < BATCH) {
        int c = y[b];
        if (c < 0) c = 0;
        if (c >= N_CLASS) c = N_CLASS - 1;   // crash-proofing; rel_err will expose misuse
        int pos = atomicAdd(&g_count[c], 1);
        g_list[c * BATCH + pos] = b;
    }
}

// One CTA per (class, center). 256 threads as 16x16; each thread owns an
// 8x8 register sub-tile of the 128x128 output (strided by 16 in both dims).
__global__ void __launch_bounds__(256, 2) cov_kernel(
    const float* __restrict__ x,          // [BATCH, HIDDEN]
    const float* __restrict__ class_mu,   // [N_CLASS, N_CENTER, HIDDEN]; only [0] used
    const float* __restrict__ class_cov,  // [N_CLASS, N_CENTER, HIDDEN, HIDDEN]
    float* __restrict__ out)              // same shape as class_cov
{
    const int c = blockIdx.x;   // class
    const int j = blockIdx.y;   // center

    __shared__ float s_mu[HIDDEN];
    __shared__ float s_d[CHUNK][HIDDEN];

    const int tid = threadIdx.x;
    const int tx = tid & 15;    // column group
    const int ty = tid >> 4;    // row group

    if (tid < HIDDEN) s_mu[tid] = class_mu[j * HIDDEN + tid];  // class_mu[0][j][:]
    __syncthreads();

    float acc[8][8];
#pragma unroll
    for (int ri = 0; ri < 8; ri++)
#pragma unroll
        for (int ci = 0; ci < 8; ci++) acc[ri][ci] = 0.0f;

    const int n = g_count[c];
    const int* list = g_list + c * BATCH;

    for (int s0 = 0; s0 < n; s0 += CHUNK) {
        const int ns = min(CHUNK, n - s0);
        // Cooperative gather of ns diff rows: ns*128 elems over 256 threads.
        for (int i = tid; i < ns * HIDDEN; i += 256) {
            const int s = i >> 7;
            const int h = i & (HIDDEN - 1);
            const int b = list[s0 + s];
            s_d[s][h] = x[b * HIDDEN + h] - s_mu[h];
        }
        __syncthreads();

        for (int s = 0; s < ns; s++) {
            float dr[8], dc[8];
#pragma unroll
            for (int ri = 0; ri < 8; ri++) dr[ri] = s_d[s][ty + 16 * ri];
#pragma unroll
            for (int ci = 0; ci < 8; ci++) dc[ci] = s_d[s][tx + 16 * ci];
#pragma unroll
            for (int ri = 0; ri < 8; ri++)
#pragma unroll
                for (int ci = 0; ci < 8; ci++)
                    acc[ri][ci] += dr[ri] * dc[ci];
        }
        __syncthreads();
    }

    // Epilogue: out = acc + class_cov. Fully coalesced (stride-1 in cc across tx).
    const size_t base = ((size_t)(c * N_CENTER + j)) * HIDDEN * HIDDEN;
#pragma unroll
    for (int ri = 0; ri < 8; ri++) {
        const int r = ty + 16 * ri;
#pragma unroll
        for (int ci = 0; ci < 8; ci++) {
            const int cc = tx + 16 * ci;
            const size_t idx = base + (size_t)r * HIDDEN + cc;
            out[idx] = acc[ri][ci] + class_cov[idx];
        }
    }
}

extern "C" void kernel_launch(void* const* d_in, const int* in_sizes, int n_in,
                              void* d_out, int out_size) {
    const float* x         = (const float*)d_in[0];
    const int*   y         = (const int*)d_in[1];
    const float* class_mu  = (const float*)d_in[2];
    const float* class_cov = (const float*)d_in[3];
    float*       out       = (float*)d_out;

    zero_counts_kernel<<<1, 128>>>();
    build_lists_kernel<<<(BATCH + 255) / 256, 256>>>(y);
    dim3 grid(N_CLASS, N_CENTER);
    cov_kernel<<<grid, 256>>>(x, class_mu, class_cov, out);
}

// round 4
// speedup vs baseline: 1.1669x; 1.1669x over previous
#include <cuda_runtime.h>

#define N_CLASS  100
#define N_CENTER 4
#define HIDDEN   128
#define BATCH    2048
#define CHUNK    16

// Single fused kernel: one CTA per (class, center).
// Phase 1: deterministic in-CTA compaction of sample indices with y[b]==c
//          (each thread scans 8 consecutive samples; warp scan + cross-warp
//           offsets give an index list ordered by b -> bitwise reproducible).
// Phase 2: smem-staged rank-k update, 8x8 register tiles per thread.
// Phase 3: coalesced epilogue out = acc + class_cov.
__global__ void __launch_bounds__(256, 2) cov_fused_kernel(
    const float* __restrict__ x,          // [BATCH, HIDDEN]
    const int*   __restrict__ y,          // [BATCH] (int32 on device)
    const float* __restrict__ class_mu,   // [N_CLASS, N_CENTER, HIDDEN]; only [0] used
    const float* __restrict__ class_cov,  // [N_CLASS, N_CENTER, HIDDEN, HIDDEN]
    float* __restrict__ out)              // same shape as class_cov
{
    const int c = blockIdx.x;   // class
    const int j = blockIdx.y;   // center

    __shared__ float s_mu[HIDDEN];
    __shared__ float s_d[CHUNK][HIDDEN];
    __shared__ int   s_list[BATCH];
    __shared__ int   s_wsum[8];

    const int tid  = threadIdx.x;
    const int lane = tid & 31;
    const int w    = tid >> 5;
    const int tx   = tid & 15;    // column group
    const int ty   = tid >> 4;    // row group

    if (tid < HIDDEN) s_mu[tid] = class_mu[j * HIDDEN + tid];  // class_mu[0][j][:]

    // ---- Phase 1: build this class's sample list (deterministic order) ----
    int loc[8];
    int cnt = 0;
    {
        const int4* y4 = (const int4*)y;            // BATCH*4B, 16B-aligned
        int4 a = y4[tid * 2];
        int4 b = y4[tid * 2 + 1];
        const int base = tid * 8;
        if (a.x == c) loc[cnt++] = base + 0;
        if (a.y == c) loc[cnt++] = base + 1;
        if (a.z == c) loc[cnt++] = base + 2;
        if (a.w == c) loc[cnt++] = base + 3;
        if (b.x == c) loc[cnt++] = base + 4;
        if (b.y == c) loc[cnt++] = base + 5;
        if (b.z == c) loc[cnt++] = base + 6;
        if (b.w == c) loc[cnt++] = base + 7;
    }
    // warp inclusive scan of cnt
    int inc = cnt;
#pragma unroll
    for (int d = 1; d < 32; d <<= 1) {
        int v = __shfl_up_sync(0xffffffffu, inc, d);
        if (lane >= d) inc += v;
    }
    if (lane == 31) s_wsum[w] = inc;
    __syncthreads();
    int woff = 0, n = 0;
#pragma unroll
    for (int k = 0; k < 8; k++) {
        int s = s_wsum[k];
        if (k < w) woff += s;
        n += s;
    }
    const int off = woff + inc - cnt;
#pragma unroll
    for (int i = 0; i < 8; i++)
        if (i < cnt) s_list[off + i] = loc[i];
    __syncthreads();

    // ---- Phase 2: rank-k accumulation ----
    float acc[8][8];
#pragma unroll
    for (int ri = 0; ri < 8; ri++)
#pragma unroll
        for (int ci = 0; ci < 8; ci++) acc[ri][ci] = 0.0f;

    const float4* x4   = (const float4*)x;
    const float4* smu4 = (const float4*)s_mu;

    for (int s0 = 0; s0 < n; s0 += CHUNK) {
        const int ns = min(CHUNK, n - s0);
        // Cooperative float4 gather: ns rows * 32 float4, over 256 threads.
        for (int i = tid; i < ns * 32; i += 256) {
            const int s = i >> 5;
            const int q = i & 31;
            const int b = s_list[s0 + s];
            float4 v = x4[b * 32 + q];
            float4 m = smu4[q];
            v.x -= m.x; v.y -= m.y; v.z -= m.z; v.w -= m.w;
            ((float4*)s_d[s])[q] = v;
        }
        __syncthreads();

        for (int s = 0; s < ns; s++) {
            float dr[8], dc[8];
#pragma unroll
            for (int ri = 0; ri < 8; ri++) dr[ri] = s_d[s][ty + 16 * ri];
#pragma unroll
            for (int ci = 0; ci < 8; ci++) dc[ci] = s_d[s][tx + 16 * ci];
#pragma unroll
            for (int ri = 0; ri < 8; ri++)
#pragma unroll
                for (int ci = 0; ci < 8; ci++)
                    acc[ri][ci] += dr[ri] * dc[ci];
        }
        __syncthreads();
    }

    // ---- Phase 3: epilogue out = acc + class_cov (fully coalesced) ----
    const size_t base = ((size_t)(c * N_CENTER + j)) * HIDDEN * HIDDEN;
#pragma unroll
    for (int ri = 0; ri < 8; ri++) {
        const int r = ty + 16 * ri;
#pragma unroll
        for (int ci = 0; ci < 8; ci++) {
            const int cc = tx + 16 * ci;
            const size_t idx = base + (size_t)r * HIDDEN + cc;
            out[idx] = acc[ri][ci] + class_cov[idx];
        }
    }
}

extern "C" void kernel_launch(void* const* d_in, const int* in_sizes, int n_in,
                              void* d_out, int out_size) {
    const float* x         = (const float*)d_in[0];
    const int*   y         = (const int*)d_in[1];
    const float* class_mu  = (const float*)d_in[2];
    const float* class_cov = (const float*)d_in[3];
    float*       out       = (float*)d_out;

    dim3 grid(N_CLASS, N_CENTER);
    cov_fused_kernel<<<grid, 256>>>(x, y, class_mu, class_cov, out);
}